// round 16
// baseline (speedup 1.0000x reference)
#include <cuda_runtime.h>
#include <cuda_fp16.h>
#include <cstdint>

#define L_SEQ 2048
#define BATCH 8
#define EMB   1024
#define KDIM  1024
#define MTOT  (BATCH * L_SEQ)   // 16384

// ---- GEMM tiling: CTA 128x128, 4 warps (2x2), warp tile 64x64, BK=64 ----
#define BM 128
#define BN 128
#define BK 64
#define NCHUNK (KDIM / BK)      // 16
#define GTHREADS 128
#define NSTAGE 3

// gmem tiled layout: [row_blk][k_blk] tiles of 128 rows x 64 halves = 16 KB,
// rows are 128B, swizzled with the SW128 XOR (bits[6:4] ^= bits[9:7]).
#define TILE_ELEMS (BM * BK)                 // 8192 halves
#define TILE_BYTES (TILE_ELEMS * 2)          // 16384
#define KTILES (KDIM / BK)                   // 16

#define STAGE_BYTES (2 * TILE_BYTES)         // 32768 (A tile + B tile)
#define SM_STAGE0 1024                       // mbarriers live below
#define SMEM_BYTES (SM_STAGE0 + NSTAGE * STAGE_BYTES)   // 99328

__device__ __forceinline__ uint32_t swz(uint32_t off) { return off ^ ((off >> 3) & 0x70); }

// ---------------- scratch (device globals) ----------------
__device__ __half g_xh[(size_t)MTOT * KDIM];   // tiled
__device__ __half g_wih[(size_t)EMB * KDIM];   // tiled
__device__ __half g_woh[(size_t)EMB * KDIM];   // tiled
__device__ __half g_v[(size_t)MTOT * EMB];     // plain (attention input)
__device__ __half g_att[(size_t)MTOT * EMB];   // tiled (GEMM2 A input)

__constant__ int c_pos[8] = {0, 1, 2, 3, 4, 0, 1, 2};
__constant__ float c_wtab[8] = {
    1.0f, 0.60653065971263342f, 0.13533528323661270f, 0.011108996538242306f,
    3.3546262790251185e-4f, 3.7266531720786709e-6f, 1.5229979744712628e-8f,
    2.2897348456455531e-11f
};

// ---------------- PTX helpers ----------------
__device__ __forceinline__ uint32_t smem_u32(const void* p) {
    uint32_t a;
    asm("{ .reg .u64 t; cvta.to.shared.u64 t, %1; cvt.u32.u64 %0, t; }" : "=r"(a) : "l"(p));
    return a;
}
__device__ __forceinline__ void mbar_init(uint32_t a, uint32_t cnt) {
    asm volatile("mbarrier.init.shared.b64 [%0], %1;" :: "r"(a), "r"(cnt) : "memory");
}
__device__ __forceinline__ void mbar_expect_tx(uint32_t a, uint32_t bytes) {
    asm volatile("mbarrier.arrive.expect_tx.shared.b64 _, [%0], %1;" :: "r"(a), "r"(bytes) : "memory");
}
__device__ __forceinline__ void mbar_arrive(uint32_t a) {
    asm volatile("mbarrier.arrive.shared.b64 _, [%0];" :: "r"(a) : "memory");
}
__device__ __forceinline__ void mbar_wait(uint32_t a, uint32_t par) {
    asm volatile("{\n\t.reg .pred P;\n\tWL_%=:\n\t"
        "mbarrier.try_wait.parity.acquire.cta.shared::cta.b64 P, [%0], %1, 0x989680;\n\t"
        "@P bra.uni WD_%=;\n\tbra.uni WL_%=;\n\tWD_%=:\n\t}" :: "r"(a), "r"(par) : "memory");
}
__device__ __forceinline__ void bulk_g2s(uint32_t dst, const void* src, uint32_t bytes, uint32_t mbar) {
    asm volatile("cp.async.bulk.shared::cluster.global.mbarrier::complete_tx::bytes [%0], [%1], %2, [%3];"
                 :: "r"(dst), "l"(src), "r"(bytes), "r"(mbar) : "memory");
}
__device__ __forceinline__ void ldx4(uint32_t* r, uint32_t addr) {
    asm volatile("ldmatrix.sync.aligned.m8n8.x4.shared.b16 {%0,%1,%2,%3}, [%4];"
                 : "=r"(r[0]), "=r"(r[1]), "=r"(r[2]), "=r"(r[3]) : "r"(addr));
}
__device__ __forceinline__ void mma16816(float* c, const uint32_t* a, const uint32_t* b) {
    asm volatile("mma.sync.aligned.m16n8k16.row.col.f32.f16.f16.f32 "
                 "{%0,%1,%2,%3}, {%4,%5,%6,%7}, {%8,%9}, {%0,%1,%2,%3};"
                 : "+f"(c[0]), "+f"(c[1]), "+f"(c[2]), "+f"(c[3])
                 : "r"(a[0]), "r"(a[1]), "r"(a[2]), "r"(a[3]), "r"(b[0]), "r"(b[1]));
}

// ---------------------------------------------------------------------------
// fp16 mma.sync GEMM on TMA bulk copies with full/empty mbarrier rings.
// C[M,N] = A[M,K] · B[N,K]^T. A,B tiled+swizzled; C plain row-major.
// full[s] @ sb + s*8 (count 1, tx-based); empty[s] @ sb + 24 + s*8 (count 4).
// NO __syncthreads in the mainloop: warps free-run, bounded by the rings.
//
// Producer parity proof: prefetching chunk j into stage j%3 must wait for the
// (j/3)-th completion of empty[j%3] (previous occupant chunk j-3, consumed at
// iteration i-1 = j-3). Wait for n-th completion uses parity (n-1)&1; n=0
// (stage untouched, j=2) needs pass-immediately = parity 1 = (0-1)&1. So
// parity = ((j/3) - 1) & 1 uniformly.
// ---------------------------------------------------------------------------
template <typename OutT>
__global__ __launch_bounds__(GTHREADS, 2)
void gemm_f16(const __half* __restrict__ A, const __half* __restrict__ B,
              OutT* __restrict__ C)
{
    extern __shared__ char smem[];
    const uint32_t sb = smem_u32(smem);
    const int tid  = threadIdx.x;
    const int lane = tid & 31, wid = tid >> 5;
    const int wm = (wid & 1) * 64, wn = (wid >> 1) * 64;
    const int row0 = blockIdx.y * BM, col0 = blockIdx.x * BN;

    const __half* Atiles = A + (size_t)blockIdx.y * KTILES * TILE_ELEMS;
    const __half* Btiles = B + (size_t)blockIdx.x * KTILES * TILE_ELEMS;

    float acc[4][8][4];
#pragma unroll
    for (int i = 0; i < 4; ++i)
#pragma unroll
        for (int j = 0; j < 8; ++j)
#pragma unroll
            for (int k = 0; k < 4; ++k) acc[i][j][k] = 0.f;

    if (tid == 0) {
#pragma unroll
        for (int s = 0; s < NSTAGE; ++s) {
            mbar_init(sb + s * 8, 1);           // full
            mbar_init(sb + 24 + s * 8, 4);      // empty (one arrive per warp)
        }
    }
    __syncthreads();    // barriers initialized before any wait/arrive

    if (tid == 0) {
#pragma unroll
        for (int c = 0; c < 2; ++c) {
            const uint32_t st = sb + SM_STAGE0 + c * STAGE_BYTES;
            mbar_expect_tx(sb + c * 8, STAGE_BYTES);
            bulk_g2s(st,              Atiles + (size_t)c * TILE_ELEMS, TILE_BYTES, sb + c * 8);
            bulk_g2s(st + TILE_BYTES, Btiles + (size_t)c * TILE_ELEMS, TILE_BYTES, sb + c * 8);
        }
    }

    int stage = 0, fphase = 0;
    for (int i = 0; i < NCHUNK; ++i) {
        mbar_wait(sb + stage * 8, fphase);      // full: chunk i resident

        // producer: prefetch chunk j=i+2 after its stage is fully released
        if (tid == 0 && i + 2 < NCHUNK) {
            const int j  = i + 2;
            const int ps = (stage + 2 >= NSTAGE) ? stage + 2 - NSTAGE : stage + 2;  // j % 3
            const uint32_t epar = (uint32_t)(((j / 3) - 1) & 1);
            mbar_wait(sb + 24 + ps * 8, epar);
            const uint32_t st = sb + SM_STAGE0 + ps * STAGE_BYTES;
            mbar_expect_tx(sb + ps * 8, STAGE_BYTES);
            bulk_g2s(st,              Atiles + (size_t)j * TILE_ELEMS, TILE_BYTES, sb + ps * 8);
            bulk_g2s(st + TILE_BYTES, Btiles + (size_t)j * TILE_ELEMS, TILE_BYTES, sb + ps * 8);
        }

        const uint32_t stA = sb + SM_STAGE0 + stage * STAGE_BYTES;
        const uint32_t stB = stA + TILE_BYTES;
        const uint32_t csel = ((lane >> 4) << 4);

        // four k-slices of 16 within the 64-wide chunk (rows are 128B)
#pragma unroll
        for (int ks = 0; ks < 4; ++ks) {
            uint32_t ah[4][4];
#pragma unroll
            for (int t = 0; t < 4; ++t) {
                const uint32_t off = (uint32_t)(wm + (lane & 15) + t * 16) * 128 + ks * 32 + csel;
                ldx4(ah[t], stA + swz(off));
            }
            uint32_t bh[8][2];
#pragma unroll
            for (int p = 0; p < 4; ++p) {
                const uint32_t off = (uint32_t)(wn + (lane & 15) + p * 16) * 128 + ks * 32 + csel;
                uint32_t r[4];
                ldx4(r, stB + swz(off));
                bh[2*p][0] = r[0]; bh[2*p][1] = r[2];
                bh[2*p+1][0] = r[1]; bh[2*p+1][1] = r[3];
            }
#pragma unroll
            for (int mt = 0; mt < 4; ++mt)
#pragma unroll
                for (int nt = 0; nt < 8; ++nt)
                    mma16816(acc[mt][nt], ah[mt], bh[nt]);
        }

        // all frags consumed by MMAs (warp-synchronous) => stage reusable
        if (lane == 0) mbar_arrive(sb + 24 + stage * 8);

        ++stage; if (stage >= NSTAGE) { stage = 0; fphase ^= 1; }
    }

    // epilogue (plain row-major C)
#pragma unroll
    for (int mt = 0; mt < 4; ++mt) {
        const int m = row0 + wm + mt * 16 + (lane >> 2);
#pragma unroll
        for (int nt = 0; nt < 8; ++nt) {
            const int n = col0 + wn + nt * 8 + (lane & 3) * 2;
            if (sizeof(OutT) == 2) {
                *(__half2*)((__half*)C + (size_t)m * EMB + n) =
                    __floats2half2_rn(acc[mt][nt][0], acc[mt][nt][1]);
                *(__half2*)((__half*)C + (size_t)(m + 8) * EMB + n) =
                    __floats2half2_rn(acc[mt][nt][2], acc[mt][nt][3]);
            } else {
                *(float2*)((float*)C + (size_t)m * EMB + n) =
                    make_float2(acc[mt][nt][0], acc[mt][nt][1]);
                *(float2*)((float*)C + (size_t)(m + 8) * EMB + n) =
                    make_float2(acc[mt][nt][2], acc[mt][nt][3]);
            }
        }
    }
}

// ---------------------------------------------------------------------------
// fp32 plain -> fp16 tiled+swizzled convert. 16 elems/thread, MLP=4.
// ---------------------------------------------------------------------------
__device__ __forceinline__ void cvt_body(const float* __restrict__ src,
                                         __half* __restrict__ dst, int i)
{
    const int m = i >> 10;            // KDIM = 1024
    const int k = i & 1023;           // multiple of 16 -> all in same 64-chunk

    float4 f[4];
#pragma unroll
    for (int c = 0; c < 4; ++c) f[c] = *(const float4*)(src + i + c * 4);

    const uint32_t tile = (uint32_t)(m >> 7) * KTILES + (k >> 6);
    char* tb = (char*)dst + (size_t)tile * TILE_BYTES;
    const uint32_t rowb = (uint32_t)(m & 127) << 7;
#pragma unroll
    for (int c = 0; c < 4; ++c) {
        __half h[4] = { __float2half_rn(f[c].x), __float2half_rn(f[c].y),
                        __float2half_rn(f[c].z), __float2half_rn(f[c].w) };
        const uint32_t o = swz(rowb | (((uint32_t)(k & 63) + c * 4) << 1));
        *(uint2*)(tb + o) = *(uint2*)h;
    }
}

__global__ __launch_bounds__(256)
void cvt_tiled_kernel(const float* __restrict__ src, __half* __restrict__ dst, int n)
{
    const int i = (blockIdx.x * 256 + threadIdx.x) * 16;
    if (i < n) cvt_body(src, dst, i);
}

// both weight matrices in one launch (blockIdx.y selects)
__global__ __launch_bounds__(256)
void cvt_w_kernel(const float* __restrict__ w1, __half* __restrict__ d1,
                  const float* __restrict__ w2, __half* __restrict__ d2)
{
    const float* src = blockIdx.y ? w2 : w1;
    __half*      dst = blockIdx.y ? d2 : d1;
    cvt_body(src, dst, (blockIdx.x * 256 + threadIdx.x) * 16);
}

// ---------------------------------------------------------------------------
// attention: banded Gaussian conv + inlined constant heads
// (plain fp16 v -> tiled att); 2 columns x 8 queries per thread, half2 stores.
// ---------------------------------------------------------------------------
#define QT 16
#define CT 256
#define KT 32

__global__ __launch_bounds__(256)
void attn_kernel(const __half* __restrict__ v, __half* __restrict__ att)
{
    const int b = blockIdx.z, q0 = blockIdx.y * QT, c0 = blockIdx.x * CT;
    const int tid = threadIdx.x;
    __shared__ float vt[KT][CT];

    const __half* vb = v + (size_t)b * L_SEQ * EMB;
#pragma unroll
    for (int i = 0; i < 8; ++i) {
        const int id = tid + i * 256;
        const int kb = id >> 6, cc = (id & 63) << 2;
        const int k  = q0 - 8 + kb;
        float4 val = make_float4(0.f, 0.f, 0.f, 0.f);
        if (k >= 0 && k < L_SEQ) {
            uint2 raw = *(const uint2*)(vb + (size_t)k * EMB + c0 + cc);
            const __half* hp = (const __half*)&raw;
            val = make_float4(__half2float(hp[0]), __half2float(hp[1]),
                              __half2float(hp[2]), __half2float(hp[3]));
        }
        *(float4*)&vt[kb][cc] = val;
    }
    __syncthreads();

    const int cp = tid & 127;          // column pair index
    const int qh = tid >> 7;           // query half: 0 or 1
    const int c  = c0 + cp * 2;        // even column
    const int h = c >> 7, pos = c_pos[h];

    const int mbase = b * L_SEQ + q0;
    const uint32_t tile = (uint32_t)(mbase >> 7) * KTILES + (c >> 6);
    char* tbase = (char*)att + (size_t)tile * TILE_BYTES;
    const uint32_t cbits = (uint32_t)(c & 63) << 1;
    const int qlo = qh * 8;

    if (pos <= 2) {
        const int off = (pos == 0) ? 0 : (pos == 1 ? -1 : 1);
#pragma unroll
        for (int qq = qlo; qq < qlo + 8; ++qq) {
            const int cen = q0 + qq + off;
            const int k0 = max(0, cen - 7), k1 = min(L_SEQ - 1, cen + 7);
            float Z = 0.f, a0 = 0.f, a1 = 0.f;
            for (int k = k0; k <= k1; ++k) {
                const int   d = k - cen;
                const float w = c_wtab[d < 0 ? -d : d];
                Z  += w;
                a0 += w * vt[k - q0 + 8][cp * 2];
                a1 += w * vt[k - q0 + 8][cp * 2 + 1];
            }
            const float inv = 1.f / Z;
            const uint32_t o = swz((((uint32_t)((mbase + qq) & 127)) << 7) | cbits);
            *(__half2*)(tbase + o) = __floats2half2_rn(a0 * inv, a1 * inv);
        }
    } else {
        // query-independent head ('first' or 'last'): 8-tap one-sided window
        const int isLast = (pos == 4);
        float Z = 0.f, a0 = 0.f, a1 = 0.f;
#pragma unroll
        for (int j = 0; j < 8; ++j) {
            const int   k = isLast ? (L_SEQ - 1 - j) : j;
            const float w = c_wtab[j];
            Z += w;
            const __half2 hv = *(const __half2*)(vb + (size_t)k * EMB + c);
            const float2 f = __half22float2(hv);
            a0 += w * f.x; a1 += w * f.y;
        }
        const float inv = 1.f / Z;
        const __half2 hh = __floats2half2_rn(a0 * inv, a1 * inv);
#pragma unroll
        for (int qq = qlo; qq < qlo + 8; ++qq) {
            const uint32_t o = swz((((uint32_t)((mbase + qq) & 127)) << 7) | cbits);
            *(__half2*)(tbase + o) = hh;
        }
    }
}

// ---------------------------------------------------------------------------
extern "C" void kernel_launch(void* const* d_in, const int* in_sizes, int n_in,
                              void* d_out, int out_size)
{
    const float* x     = (const float*)d_in[0];
    const float* W_in  = (const float*)d_in[1];
    const float* W_out = (const float*)d_in[2];
    float* out = (float*)d_out;

    __half *xh, *wih, *woh, *att, *v;
    cudaGetSymbolAddress((void**)&xh,  g_xh);
    cudaGetSymbolAddress((void**)&wih, g_wih);
    cudaGetSymbolAddress((void**)&woh, g_woh);
    cudaGetSymbolAddress((void**)&att, g_att);
    cudaGetSymbolAddress((void**)&v,   g_v);

    static bool attr_done = false;
    if (!attr_done) {
        cudaFuncSetAttribute(gemm_f16<__half>, cudaFuncAttributeMaxDynamicSharedMemorySize, SMEM_BYTES);
        cudaFuncSetAttribute(gemm_f16<float>,  cudaFuncAttributeMaxDynamicSharedMemorySize, SMEM_BYTES);
        attr_done = true;
    }

    const int NX = MTOT * KDIM, NW = EMB * KDIM;
    cvt_tiled_kernel<<<NX / (256 * 16), 256>>>(x, xh, NX);
    cvt_w_kernel<<<dim3(NW / (256 * 16), 2), 256>>>(W_in, wih, W_out, woh);

    const dim3 ggrid(EMB / BN, MTOT / BM);   // (8, 128)
    gemm_f16<__half><<<ggrid, GTHREADS, SMEM_BYTES>>>(xh, wih, v);

    attn_kernel<<<dim3(EMB / CT, L_SEQ / QT, BATCH), 256>>>(v, att);

    gemm_f16<float><<<ggrid, GTHREADS, SMEM_BYTES>>>(att, woh, out);
}